// round 2
// baseline (speedup 1.0000x reference)
#include <cuda_runtime.h>

// GumbelSinkhorn: B=128, N=512 (agents/rows), M=512 (tasks/cols), tau=1, 5 iters.
// Invariant: g_E holds exp(x_k) over the active [na, nt] region.
// g_rsum / g_csum hold RECIPROCAL sums of exp over rows / cols.

#define BB 128
#define NN 512
#define MM 512

__device__ float g_E[(size_t)BB * NN * MM];   // 128 MB scratch
__device__ float g_rsum[BB * NN];
__device__ float g_csum[BB * MM];

__device__ __forceinline__ float warp_sum(float v) {
    v += __shfl_xor_sync(0xffffffffu, v, 16);
    v += __shfl_xor_sync(0xffffffffu, v, 8);
    v += __shfl_xor_sync(0xffffffffu, v, 4);
    v += __shfl_xor_sync(0xffffffffu, v, 2);
    v += __shfl_xor_sync(0xffffffffu, v, 1);
    return v;
}

// ---------------------------------------------------------------------------
// init: E0 = exp(logits) over active region; rsum = 1/rowsum(E0).
// Row strips of 32. grid(16, B), block 256 (8 warps; warp owns 4 rows).
__global__ void init_kernel(const float* __restrict__ logits,
                            const int* __restrict__ fa,
                            const int* __restrict__ ta) {
    int b = blockIdx.y;
    int na = fa[b], nt = ta[b];
    int r0 = blockIdx.x * 32;
    if (r0 >= na || nt == 0) return;
    int w = threadIdx.x >> 5, lane = threadIdx.x & 31;
    const float* Lb = logits + (size_t)b * NN * MM;
    float*       Eb = g_E    + (size_t)b * NN * MM;
    for (int rr = w; rr < 32; rr += 8) {
        int r = r0 + rr;
        if (r >= na) break;
        float4 acc = make_float4(0.f, 0.f, 0.f, 0.f);
        #pragma unroll 2
        for (int cb = lane * 4; cb < nt; cb += 128) {
            int nv = nt - cb;
            if (nv >= 4) {
                float4 e = *(const float4*)(Lb + r * MM + cb);
                e.x = __expf(e.x); e.y = __expf(e.y);
                e.z = __expf(e.z); e.w = __expf(e.w);
                *(float4*)(Eb + r * MM + cb) = e;
                acc.x += e.x; acc.y += e.y; acc.z += e.z; acc.w += e.w;
            } else {
                for (int j = 0; j < nv; j++) {
                    float e = __expf(Lb[r * MM + cb + j]);
                    Eb[r * MM + cb + j] = e;
                    ((float*)&acc)[j] += e;
                }
            }
        }
        float s = warp_sum(acc.x + acc.y + acc.z + acc.w);
        if (lane == 0) g_rsum[b * NN + r] = 1.0f / s;
    }
}

// ---------------------------------------------------------------------------
// rownorm: E' = exp(E * rsum[r]); csum[c] = 1/sum_r E'.
// Column strips of 128 (lane owns 4 contiguous cols). grid(4, B), block 256.
__global__ void rownorm_kernel(const int* __restrict__ fa,
                               const int* __restrict__ ta) {
    int b = blockIdx.y;
    int na = fa[b], nt = ta[b];
    int c0 = blockIdx.x * 128;
    if (c0 >= nt || na == 0) return;
    int w = threadIdx.x >> 5, lane = threadIdx.x & 31;
    int cbase = c0 + lane * 4;
    int nv = nt - cbase; nv = nv < 0 ? 0 : (nv > 4 ? 4 : nv);
    float*       Eb = g_E    + (size_t)b * NN * MM;
    const float* rs = g_rsum + b * NN;
    float4 acc = make_float4(0.f, 0.f, 0.f, 0.f);
    if (nv == 4) {
        #pragma unroll 2
        for (int r = w; r < na; r += 8) {
            float inv = rs[r];
            float4 e = *(const float4*)(Eb + r * MM + cbase);
            e.x = __expf(e.x * inv); e.y = __expf(e.y * inv);
            e.z = __expf(e.z * inv); e.w = __expf(e.w * inv);
            *(float4*)(Eb + r * MM + cbase) = e;
            acc.x += e.x; acc.y += e.y; acc.z += e.z; acc.w += e.w;
        }
    } else if (nv > 0) {
        for (int r = w; r < na; r += 8) {
            float inv = rs[r];
            for (int j = 0; j < nv; j++) {
                float e = Eb[r * MM + cbase + j];
                e = __expf(e * inv);
                Eb[r * MM + cbase + j] = e;
                ((float*)&acc)[j] += e;
            }
        }
    }
    __shared__ float4 s[8][32];
    s[w][lane] = acc;
    __syncthreads();
    int t = threadIdx.x;
    if (t < 128) {
        int ln = t >> 2, comp = t & 3;
        float sum = 0.f;
        #pragma unroll
        for (int k = 0; k < 8; k++) sum += ((const float*)&s[k][ln])[comp];
        int c = c0 + t;
        if (c < nt) g_csum[b * MM + c] = 1.0f / sum;
    }
}

// ---------------------------------------------------------------------------
// colnorm: E' = exp(E * csum[c]); rsum[r] = 1/sum_c E'.
// Row strips of 32. grid(16, B), block 256.
__global__ void colnorm_kernel(const int* __restrict__ fa,
                               const int* __restrict__ ta) {
    int b = blockIdx.y;
    int na = fa[b], nt = ta[b];
    int r0 = blockIdx.x * 32;
    if (r0 >= na || nt == 0) return;
    int w = threadIdx.x >> 5, lane = threadIdx.x & 31;
    float*       Eb = g_E    + (size_t)b * NN * MM;
    const float* cs = g_csum + b * MM;
    for (int rr = w; rr < 32; rr += 8) {
        int r = r0 + rr;
        if (r >= na) break;
        float4 acc = make_float4(0.f, 0.f, 0.f, 0.f);
        #pragma unroll 2
        for (int cb = lane * 4; cb < nt; cb += 128) {
            int nv = nt - cb;
            if (nv >= 4) {
                float4 e  = *(const float4*)(Eb + r * MM + cb);
                float4 c4 = *(const float4*)(cs + cb);
                e.x = __expf(e.x * c4.x); e.y = __expf(e.y * c4.y);
                e.z = __expf(e.z * c4.z); e.w = __expf(e.w * c4.w);
                *(float4*)(Eb + r * MM + cb) = e;
                acc.x += e.x; acc.y += e.y; acc.z += e.z; acc.w += e.w;
            } else {
                for (int j = 0; j < nv; j++) {
                    float e = Eb[r * MM + cb + j];
                    e = __expf(e * cs[cb + j]);
                    Eb[r * MM + cb + j] = e;
                    ((float*)&acc)[j] += e;
                }
            }
        }
        float s = warp_sum(acc.x + acc.y + acc.z + acc.w);
        if (lane == 0) g_rsum[b * NN + r] = 1.0f / s;
    }
}

// ---------------------------------------------------------------------------
// finalize: out = E * csum[c] inside mask, 0 outside. Full coverage.
// Row strips of 32. grid(16, B), block 256. Always float4 stores (MM%128==0).
__global__ void finalize_kernel(float* __restrict__ out,
                                const int* __restrict__ fa,
                                const int* __restrict__ ta) {
    int b = blockIdx.y;
    int na = fa[b], nt = ta[b];
    int r0 = blockIdx.x * 32;
    int w = threadIdx.x >> 5, lane = threadIdx.x & 31;
    const float* Eb = g_E    + (size_t)b * NN * MM;
    const float* cs = g_csum + b * MM;
    float*       Ob = out    + (size_t)b * NN * MM;
    for (int rr = w; rr < 32; rr += 8) {
        int r = r0 + rr;
        bool rv = (r < na);
        #pragma unroll 2
        for (int cb = lane * 4; cb < MM; cb += 128) {
            float4 v = make_float4(0.f, 0.f, 0.f, 0.f);
            if (rv && cb < nt) {
                int nv = nt - cb;
                if (nv >= 4) {
                    float4 e  = *(const float4*)(Eb + r * MM + cb);
                    float4 c4 = *(const float4*)(cs + cb);
                    v.x = e.x * c4.x; v.y = e.y * c4.y;
                    v.z = e.z * c4.z; v.w = e.w * c4.w;
                } else {
                    for (int j = 0; j < nv; j++)
                        ((float*)&v)[j] = Eb[r * MM + cb + j] * cs[cb + j];
                }
            }
            *(float4*)(Ob + r * MM + cb) = v;
        }
    }
}

extern "C" void kernel_launch(void* const* d_in, const int* in_sizes, int n_in,
                              void* d_out, int out_size) {
    const float* logits = (const float*)d_in[0];
    const int*   fa     = (const int*)d_in[1];
    const int*   ta     = (const int*)d_in[2];
    float*       out    = (float*)d_out;

    dim3 block(256);
    dim3 gridR(16, BB);   // row-strip kernels
    dim3 gridC(4,  BB);   // column-strip kernels

    init_kernel<<<gridR, block>>>(logits, fa, ta);
    for (int i = 0; i < 5; i++) {
        rownorm_kernel<<<gridC, block>>>(fa, ta);
        if (i < 4) colnorm_kernel<<<gridR, block>>>(fa, ta);
    }
    finalize_kernel<<<gridR, block>>>(out, fa, ta);
}

// round 3
// speedup vs baseline: 1.8129x; 1.8129x over previous
#include <cuda_runtime.h>

// GumbelSinkhorn: B=128, N=512 (rows/agents), M=512 (cols/tasks), tau=1, 5 iters.
// Invariant: g_E holds exp(x_k) over the active [na, nt] region.
// g_rsum / g_csum hold RECIPROCAL sums of exp over rows / cols.

#define BB 128
#define NN 512
#define MM 512

__device__ float g_E[(size_t)BB * NN * MM];
__device__ float g_rsum[BB * NN];
__device__ float g_csum[BB * MM];

__device__ __forceinline__ float warp_sum(float v) {
    v += __shfl_xor_sync(0xffffffffu, v, 16);
    v += __shfl_xor_sync(0xffffffffu, v, 8);
    v += __shfl_xor_sync(0xffffffffu, v, 4);
    v += __shfl_xor_sync(0xffffffffu, v, 2);
    v += __shfl_xor_sync(0xffffffffu, v, 1);
    return v;
}

// ---------------------------------------------------------------------------
// init: E0 = exp(logits) on active region; rsum = 1/rowsum.
// 32-row strips, grid(16,B), block 512 (16 warps -> 2 rows per warp).
__global__ void __launch_bounds__(512) init_kernel(
        const float* __restrict__ logits,
        const int* __restrict__ fa,
        const int* __restrict__ ta) {
    int b = blockIdx.y;
    int na = fa[b], nt = ta[b];
    int r0 = blockIdx.x * 32;
    if (r0 >= na || nt == 0) return;
    int w = threadIdx.x >> 5, lane = threadIdx.x & 31;
    const float* Lb = logits + (size_t)b * NN * MM;
    float*       Eb = g_E    + (size_t)b * NN * MM;
    int cb0 = lane * 4;
    for (int rr = w; rr < 32; rr += 16) {
        int r = r0 + rr;
        if (r >= na) break;
        float4 acc = make_float4(0.f, 0.f, 0.f, 0.f);
        #pragma unroll
        for (int k = 0; k < 4; k++) {
            int cb = cb0 + k * 128;
            if (cb >= nt) continue;
            int nv = nt - cb;
            if (nv >= 4) {
                float4 e = *(const float4*)(Lb + r * MM + cb);
                e.x = __expf(e.x); e.y = __expf(e.y);
                e.z = __expf(e.z); e.w = __expf(e.w);
                *(float4*)(Eb + r * MM + cb) = e;
                acc.x += e.x; acc.y += e.y; acc.z += e.z; acc.w += e.w;
            } else {
                for (int j = 0; j < nv; j++) {
                    float e = __expf(Lb[r * MM + cb + j]);
                    Eb[r * MM + cb + j] = e;
                    ((float*)&acc)[j] += e;
                }
            }
        }
        float s = warp_sum(acc.x + acc.y + acc.z + acc.w);
        if (lane == 0) g_rsum[b * NN + r] = 1.0f / s;
    }
}

// ---------------------------------------------------------------------------
// rownorm: E' = exp(E * rsum[r]); csum[c] = 1/sum_r E'.
// 64-col strips, grid(8,B), block 512. Lane owns 2 cols (float2).
// Rows strided by 16 with explicit 4-deep pipeline (MLP ~8 loads).
__global__ void __launch_bounds__(512) rownorm_kernel(
        const int* __restrict__ fa,
        const int* __restrict__ ta) {
    int b = blockIdx.y;
    int na = fa[b], nt = ta[b];
    int c0 = blockIdx.x * 64;
    if (c0 >= nt || na == 0) return;
    int w = threadIdx.x >> 5, lane = threadIdx.x & 31;
    int c = c0 + lane * 2;
    float*       Eb = g_E    + (size_t)b * NN * MM;
    const float* rs = g_rsum + b * NN;
    float2 acc = make_float2(0.f, 0.f);

    if (c + 1 < nt) {
        int r = w;
        for (; r + 48 < na; r += 64) {
            float2 e0 = *(const float2*)(Eb + (r     ) * MM + c);
            float2 e1 = *(const float2*)(Eb + (r + 16) * MM + c);
            float2 e2 = *(const float2*)(Eb + (r + 32) * MM + c);
            float2 e3 = *(const float2*)(Eb + (r + 48) * MM + c);
            float i0 = rs[r], i1 = rs[r + 16], i2 = rs[r + 32], i3 = rs[r + 48];
            e0.x = __expf(e0.x * i0); e0.y = __expf(e0.y * i0);
            e1.x = __expf(e1.x * i1); e1.y = __expf(e1.y * i1);
            e2.x = __expf(e2.x * i2); e2.y = __expf(e2.y * i2);
            e3.x = __expf(e3.x * i3); e3.y = __expf(e3.y * i3);
            *(float2*)(Eb + (r     ) * MM + c) = e0;
            *(float2*)(Eb + (r + 16) * MM + c) = e1;
            *(float2*)(Eb + (r + 32) * MM + c) = e2;
            *(float2*)(Eb + (r + 48) * MM + c) = e3;
            acc.x += e0.x + e1.x + e2.x + e3.x;
            acc.y += e0.y + e1.y + e2.y + e3.y;
        }
        for (; r < na; r += 16) {
            float2 e = *(const float2*)(Eb + r * MM + c);
            float inv = rs[r];
            e.x = __expf(e.x * inv); e.y = __expf(e.y * inv);
            *(float2*)(Eb + r * MM + c) = e;
            acc.x += e.x; acc.y += e.y;
        }
    } else if (c < nt) {
        for (int r = w; r < na; r += 16) {
            float e = Eb[r * MM + c];
            e = __expf(e * rs[r]);
            Eb[r * MM + c] = e;
            acc.x += e;
        }
    }

    __shared__ float2 s[16][32];
    s[w][lane] = acc;
    __syncthreads();
    int t = threadIdx.x;
    if (t < 64) {
        int ln = t >> 1, comp = t & 1;
        float sum = 0.f;
        #pragma unroll
        for (int k = 0; k < 16; k++) sum += ((const float*)&s[k][ln])[comp];
        int cc = c0 + t;
        if (cc < nt) g_csum[b * MM + cc] = 1.0f / sum;
    }
}

// ---------------------------------------------------------------------------
// colnorm: E' = exp(E * csum[c]); rsum[r] = 1/sum_c E'.
// 32-row strips, grid(16,B), block 512 (2 rows per warp), float4 cols.
__global__ void __launch_bounds__(512) colnorm_kernel(
        const int* __restrict__ fa,
        const int* __restrict__ ta) {
    int b = blockIdx.y;
    int na = fa[b], nt = ta[b];
    int r0 = blockIdx.x * 32;
    if (r0 >= na || nt == 0) return;
    int w = threadIdx.x >> 5, lane = threadIdx.x & 31;
    float*       Eb = g_E    + (size_t)b * NN * MM;
    const float* cs = g_csum + b * MM;
    int cb0 = lane * 4;
    for (int rr = w; rr < 32; rr += 16) {
        int r = r0 + rr;
        if (r >= na) break;
        float4 acc = make_float4(0.f, 0.f, 0.f, 0.f);
        #pragma unroll
        for (int k = 0; k < 4; k++) {
            int cb = cb0 + k * 128;
            if (cb >= nt) continue;
            int nv = nt - cb;
            if (nv >= 4) {
                float4 e  = *(const float4*)(Eb + r * MM + cb);
                float4 c4 = *(const float4*)(cs + cb);
                e.x = __expf(e.x * c4.x); e.y = __expf(e.y * c4.y);
                e.z = __expf(e.z * c4.z); e.w = __expf(e.w * c4.w);
                *(float4*)(Eb + r * MM + cb) = e;
                acc.x += e.x; acc.y += e.y; acc.z += e.z; acc.w += e.w;
            } else {
                for (int j = 0; j < nv; j++) {
                    float e = Eb[r * MM + cb + j];
                    e = __expf(e * cs[cb + j]);
                    Eb[r * MM + cb + j] = e;
                    ((float*)&acc)[j] += e;
                }
            }
        }
        float s = warp_sum(acc.x + acc.y + acc.z + acc.w);
        if (lane == 0) g_rsum[b * NN + r] = 1.0f / s;
    }
}

// ---------------------------------------------------------------------------
// finalize: out = E * csum[c] in mask, 0 outside. Full [N,M] coverage.
// 32-row strips, grid(16,B), block 512, float4 stores (MM = 4*128).
__global__ void __launch_bounds__(512) finalize_kernel(
        float* __restrict__ out,
        const int* __restrict__ fa,
        const int* __restrict__ ta) {
    int b = blockIdx.y;
    int na = fa[b], nt = ta[b];
    int r0 = blockIdx.x * 32;
    int w = threadIdx.x >> 5, lane = threadIdx.x & 31;
    const float* Eb = g_E    + (size_t)b * NN * MM;
    const float* cs = g_csum + b * MM;
    float*       Ob = out    + (size_t)b * NN * MM;
    int cb0 = lane * 4;
    for (int rr = w; rr < 32; rr += 16) {
        int r = r0 + rr;
        bool rv = (r < na);
        #pragma unroll
        for (int k = 0; k < 4; k++) {
            int cb = cb0 + k * 128;
            float4 v = make_float4(0.f, 0.f, 0.f, 0.f);
            if (rv && cb < nt) {
                int nv = nt - cb;
                if (nv >= 4) {
                    float4 e  = *(const float4*)(Eb + r * MM + cb);
                    float4 c4 = *(const float4*)(cs + cb);
                    v.x = e.x * c4.x; v.y = e.y * c4.y;
                    v.z = e.z * c4.z; v.w = e.w * c4.w;
                } else {
                    for (int j = 0; j < nv; j++)
                        ((float*)&v)[j] = Eb[r * MM + cb + j] * cs[cb + j];
                }
            }
            *(float4*)(Ob + r * MM + cb) = v;
        }
    }
}

extern "C" void kernel_launch(void* const* d_in, const int* in_sizes, int n_in,
                              void* d_out, int out_size) {
    const float* logits = (const float*)d_in[0];
    const int*   fa     = (const int*)d_in[1];
    const int*   ta     = (const int*)d_in[2];
    float*       out    = (float*)d_out;

    dim3 block(512);
    dim3 gridR(16, BB);   // row-strip kernels
    dim3 gridC(8,  BB);   // column-strip kernels (64-col strips)

    init_kernel<<<gridR, block>>>(logits, fa, ta);
    for (int i = 0; i < 5; i++) {
        rownorm_kernel<<<gridC, block>>>(fa, ta);
        if (i < 4) colnorm_kernel<<<gridR, block>>>(fa, ta);
    }
    finalize_kernel<<<gridR, block>>>(out, fa, ta);
}